// round 10
// baseline (speedup 1.0000x reference)
#include <cuda_runtime.h>
#include <math.h>

#define IMG_W 8192
typedef unsigned long long ull;

// ---------------- scratch ----------------
// acc0 64x128x128 @0, acc1 64x64x64 @1048576, acc2 64x32x32 @1310720,
// acc3 64x16x16 @1376256, acc4 64x8x8 @1392640
__device__ float g_accs[1396736];
__device__ int   g_bounds[4] = {1 << 30, -1, 1 << 30, -1};  // idempotent atomics -> replay-safe
__device__ float g_scale[320];
__device__ float g_shift[320];
__device__ unsigned g_count = 0;   // grid barrier arrive counter (self-resetting)
__device__ unsigned g_gen   = 0;   // grid barrier generation (monotone -> replay-safe)

#define PACK2(dst, v)  asm("mov.b64 %0, {%1, %1};" : "=l"(dst) : "r"(__float_as_uint(v)))
#define FMA2(acc, a, b) asm("fma.rn.f32x2 %0, %1, %2, %0;" : "+l"(acc) : "l"(a), "l"(b))
#define UNPACK2(lo, hi, v) asm("mov.b64 {%0, %1}, %2;" : "=r"(lo), "=r"(hi) : "l"(v))

template<int L> struct Offs;
template<> struct Offs<0> { static const int v = 0; };
template<> struct Offs<1> { static const int v = 1048576; };
template<> struct Offs<2> { static const int v = 1310720; };
template<> struct Offs<3> { static const int v = 1376256; };
template<> struct Offs<4> { static const int v = 1392640; };

// ---------------- grid-wide barrier (all blocks resident by construction) --------
__device__ __forceinline__ void gsync()
{
    __syncthreads();
    if (threadIdx.x == 0) {
        __threadfence();
        unsigned gen = *(volatile unsigned*)&g_gen;
        if (atomicAdd(&g_count, 1u) == gridDim.x - 1) {
            atomicExch(&g_count, 0u);        // reset BEFORE release
            __threadfence();
            atomicExch(&g_gen, gen + 1u);    // release
        } else {
            while (*(volatile unsigned*)&g_gen == gen) { __nanosleep(64); }
        }
    }
    __syncthreads();
}

// ---------------- scan (merged with prep work) ------------------------------------
__global__ void scan_kernel(const float* __restrict__ img,
                            const float* __restrict__ conv0_b,
                            const float* __restrict__ convs_b,
                            const float* __restrict__ gamma,
                            const float* __restrict__ beta,
                            const float* __restrict__ mean,
                            const float* __restrict__ var)
{
    __shared__ int smn[256], smx[256];
    const int b = blockIdx.x, tid = threadIdx.x;
    const int gid = b * 256 + tid;

    for (int k = gid; k < 348160; k += 1056 * 256) g_accs[1048576 + k] = 0.0f;
    if (gid < 320) {
        int l = gid >> 6, c = gid & 63;
        float sc = gamma[gid] / sqrtf(var[gid] + 1e-5f);
        float bb = (l == 0) ? conv0_b[c] : convs_b[(l - 1) * 64 + c];
        g_scale[gid] = sc;
        g_shift[gid] = (bb - mean[gid]) * sc + beta[gid];
    }

    int mn = 1 << 30, mx = -1;
    int lo_idx, hi_idx;
    if (b < 32) {                     // column scan, early exit
        lo_idx = 2; hi_idx = 3;
        int c = b * 256 + tid;
        float ref = img[c];
        bool found = false;
        for (int r = 1; r < IMG_W; r++) {
            found |= (img[(size_t)r * IMG_W + c] != ref);
            if (__all_sync(0xffffffffu, found)) break;
        }
        if (found) { mn = c; mx = c; }
    } else {                          // row scan, warp per row
        lo_idx = 0; hi_idx = 1;
        int row = (b - 32) * 8 + (tid >> 5);
        int lane = tid & 31;
        const float* rowp = img + (size_t)row * IMG_W;
        float v = rowp[lane];
        float ref = __shfl_sync(0xffffffffu, v, 0);
        int flag = __any_sync(0xffffffffu, v != ref) ? 1 : 0;
        for (int base = 32; base < IMG_W && !flag; base += 32)
            flag = __any_sync(0xffffffffu, rowp[base + lane] != ref) ? 1 : 0;
        if (lane == 0 && flag) { mn = row; mx = row; }
    }

    smn[tid] = mn; smx[tid] = mx;
    __syncthreads();
    for (int s = 128; s > 0; s >>= 1) {
        if (tid < s) { smn[tid] = min(smn[tid], smn[tid + s]); smx[tid] = max(smx[tid], smx[tid + s]); }
        __syncthreads();
    }
    if (tid == 0 && smx[0] >= 0) {
        atomicMin(&g_bounds[lo_idx], smn[0]);
        atomicMax(&g_bounds[hi_idx], smx[0]);
    }
}

// ---------------- fused crop/resize + dilate + conv0 (8x8 tiles, 256 blocks) -----
__global__ void front_kernel(const float* __restrict__ img, const float* __restrict__ w0)
{
    __shared__ float s_res[21 * 21];
    __shared__ float s_dil[17 * 17];
    __shared__ float s_w[576];
    const int b = blockIdx.x, tid = threadIdx.x;
    const int ty = b >> 4, tx = b & 15;
    const int oy0 = ty * 8, ox0 = tx * 8;

    int top = g_bounds[0], bottom = g_bounds[1], left = g_bounds[2], right = g_bounds[3];
    if (bottom < 0) { top = 0; bottom = IMG_W - 1; }
    if (right  < 0) { left = 0; right  = IMG_W - 1; }

    for (int i = tid; i < 576; i += 256) s_w[i] = w0[i];

    const int ry0 = 2 * oy0 - 3, rx0 = 2 * ox0 - 3;
    const float szy = (float)(bottom - top + 1);
    const float szx = (float)(right - left + 1);
    for (int i = tid; i < 21 * 21; i += 256) {
        int r = i / 21, c = i - r * 21;
        int gy = ry0 + r, gx = rx0 + c;
        float val = 0.0f;
        if ((unsigned)gy < 256u && (unsigned)gx < 256u) {
            float cy = (float)top  + ((float)gy + 0.5f) * szy * (1.0f / 256.0f) - 0.5f;
            float cx = (float)left + ((float)gx + 0.5f) * szx * (1.0f / 256.0f) - 0.5f;
            float fy0 = floorf(cy), fx0 = floorf(cx);
            float wy = cy - fy0, wx = cx - fx0;
            int y0 = (int)fminf(fmaxf(fy0,        (float)top),  (float)bottom);
            int y1 = (int)fminf(fmaxf(fy0 + 1.0f, (float)top),  (float)bottom);
            int x0 = (int)fminf(fmaxf(fx0,        (float)left), (float)right);
            int x1 = (int)fminf(fmaxf(fx0 + 1.0f, (float)left), (float)right);
            float v00 = img[(size_t)y0 * IMG_W + x0];
            float v01 = img[(size_t)y0 * IMG_W + x1];
            float v10 = img[(size_t)y1 * IMG_W + x0];
            float v11 = img[(size_t)y1 * IMG_W + x1];
            float tr = v00 * (1.0f - wx) + v01 * wx;
            float br = v10 * (1.0f - wx) + v11 * wx;
            val = 255.0f - (tr * (1.0f - wy) + br * wy);
        }
        s_res[i] = val;
    }
    __syncthreads();

    for (int i = tid; i < 17 * 17; i += 256) {
        int r = i / 17, c = i - r * 17;
        int gy = 2 * oy0 - 1 + r, gx = 2 * ox0 - 1 + c;
        float val = 0.0f;
        if ((unsigned)gy < 256u && (unsigned)gx < 256u) {
            float s = 0.0f;
            #pragma unroll
            for (int dy = 0; dy <= 4; dy += 2)
                #pragma unroll
                for (int dx = 0; dx <= 4; dx += 2)
                    s += s_res[(r + dy) * 21 + (c + dx)];
            val = 255.0f - fminf(fmaxf(s, 0.0f), 255.0f);
        }
        s_dil[i] = val;
    }
    __syncthreads();

    const int px = tid >> 2, ocq = tid & 3;
    const int ly = px >> 3, lx = px & 7;
    float v[9];
    #pragma unroll
    for (int ky = 0; ky < 3; ky++)
        #pragma unroll
        for (int kx = 0; kx < 3; kx++)
            v[ky * 3 + kx] = s_dil[(2 * ly + ky) * 17 + (2 * lx + kx)];

    const int oy = oy0 + ly, ox = ox0 + lx;
    #pragma unroll 4
    for (int j = 0; j < 16; j++) {
        int oc = ocq * 16 + j;
        float a = 0.0f;
        #pragma unroll
        for (int k = 0; k < 9; k++) a = fmaf(v[k], s_w[oc * 9 + k], a);
        g_accs[(oc * 128 + oy) * 128 + ox] = a;
    }
}

// ---------------- conv1: 8x8-tile, all-64-oc kernel (champion, unchanged) --------
template<int LAYER, int ICS>
__global__ void __launch_bounds__(256, 3) conv88_kernel(const float* __restrict__ convs_w)
{
    constexpr int HIN  = 256 >> LAYER;
    constexpr int HOUT = HIN >> 1;
    constexpr int TILESX = HOUT >> 3;
    const int tile = blockIdx.x;
    const int ty = tile / TILESX, tx = tile - ty * TILESX;
    const int oy0 = ty * 8, ox0 = tx * 8;
    const int ic0 = blockIdx.y * ICS;

    const float* __restrict__ in  = g_accs + Offs<LAYER - 1>::v;
    float* __restrict__ out       = g_accs + Offs<LAYER>::v;
    const float* __restrict__ w   = convs_w + (LAYER - 1) * 36864;
    const float* __restrict__ scl = g_scale + (LAYER - 1) * 64;
    const float* __restrict__ shf = g_shift + (LAYER - 1) * 64;

    __shared__ __align__(16) float s_w[ICS * 576];
    __shared__ __align__(16) float s_in[ICS * 340];

    const int tid = threadIdx.x;

    constexpr int WPO2 = ICS * 9 / 2;
    constexpr int W2 = 64 * WPO2;
    constexpr int W2IT = (W2 + 255) / 256;
    float2 wq[W2IT];
    #pragma unroll
    for (int i = 0; i < W2IT; i++) {
        int idx = tid + i * 256;
        if (idx < W2) {
            int oc = idx / WPO2, rem2 = idx - oc * WPO2;
            wq[i] = *reinterpret_cast<const float2*>(&w[oc * 576 + ic0 * 9 + rem2 * 2]);
        }
    }

    constexpr int ITOT = ICS * 289;
    constexpr int IIT = (ITOT + 255) / 256;
    float it[IIT];
    const int iy0 = oy0 * 2 - 1, ix0 = ox0 * 2 - 1;
    #pragma unroll
    for (int i = 0; i < IIT; i++) {
        int idx = tid + i * 256;
        if (idx < ITOT) {
            int ch = idx / 289, pos = idx - ch * 289;
            int r = pos / 17, c = pos - r * 17;
            int gy = iy0 + r, gx = ix0 + c;
            bool inb = ((unsigned)gy < (unsigned)HIN) && ((unsigned)gx < (unsigned)HIN);
            it[i] = inb ? __ldg(&in[(ic0 + ch) * HIN * HIN + gy * HIN + gx]) : 0.0f;
        }
    }

    #pragma unroll
    for (int i = 0; i < W2IT; i++) {
        int idx = tid + i * 256;
        if (idx < W2) {
            int oc = idx / WPO2, rem2 = idx - oc * WPO2;
            int f0 = rem2 * 2;
            int ic_a = f0 / 9, k_a = f0 - ic_a * 9;
            s_w[(ic_a * 9 + k_a) * 64 + oc] = wq[i].x;
            int f1 = f0 + 1;
            int ic_b = f1 / 9, k_b = f1 - ic_b * 9;
            s_w[(ic_b * 9 + k_b) * 64 + oc] = wq[i].y;
        }
    }
    #pragma unroll
    for (int i = 0; i < IIT; i++) {
        int idx = tid + i * 256;
        if (idx < ITOT) {
            int ch = idx / 289, pos = idx - ch * 289;
            int r = pos / 17, c = pos - r * 17;
            int ic = ic0 + ch;
            s_in[ch * 340 + r * 20 + c] =
                fmaxf(fmaf(it[i], __ldg(&scl[ic]), __ldg(&shf[ic])), 0.0f);
        }
    }
    __syncthreads();

    const int ocg = tid & 15;
    const int sps = tid >> 4;
    const int my = sps >> 2, mx = sps & 3;

    ull acc[2][4];
    #pragma unroll
    for (int j = 0; j < 2; j++)
        #pragma unroll
        for (int p = 0; p < 4; p++) acc[j][p] = 0ull;

    const float* bp = s_in + (4 * my) * 20 + 4 * mx;

    float4 q[5]; float e[5];
    #pragma unroll
    for (int r = 0; r < 5; r++) {
        q[r] = *reinterpret_cast<const float4*>(bp + r * 20);
        e[r] = bp[r * 20 + 4];
    }

    #pragma unroll
    for (int icc = 0; icc < ICS; icc++) {
        float4 qn[5]; float en[5];
        if (icc + 1 < ICS) {
            const float* bpn = bp + (icc + 1) * 340;
            #pragma unroll
            for (int r = 0; r < 5; r++) {
                qn[r] = *reinterpret_cast<const float4*>(bpn + r * 20);
                en[r] = bpn[r * 20 + 4];
            }
        }
        float win[5][5];
        #pragma unroll
        for (int r = 0; r < 5; r++) {
            win[r][0] = q[r].x; win[r][1] = q[r].y;
            win[r][2] = q[r].z; win[r][3] = q[r].w; win[r][4] = e[r];
        }
        #pragma unroll
        for (int ky = 0; ky < 3; ky++)
            #pragma unroll
            for (int kx = 0; kx < 3; kx++) {
                const int k = ky * 3 + kx;
                ulonglong2 wv = reinterpret_cast<const ulonglong2*>(s_w)[(icc * 9 + k) * 16 + ocg];
                #pragma unroll
                for (int py = 0; py < 2; py++)
                    #pragma unroll
                    for (int px = 0; px < 2; px++) {
                        ull v2;
                        PACK2(v2, win[2 * py + ky][2 * px + kx]);
                        const int p = py * 2 + px;
                        FMA2(acc[0][p], v2, wv.x);
                        FMA2(acc[1][p], v2, wv.y);
                    }
            }
        if (icc + 1 < ICS) {
            #pragma unroll
            for (int r = 0; r < 5; r++) { q[r] = qn[r]; e[r] = en[r]; }
        }
    }

    #pragma unroll
    for (int j = 0; j < 2; j++)
        #pragma unroll
        for (int py = 0; py < 2; py++)
            #pragma unroll
            for (int px = 0; px < 2; px++) {
                unsigned lo, hi;
                UNPACK2(lo, hi, acc[j][py * 2 + px]);
                int oy = oy0 + 2 * my + py, ox = ox0 + 2 * mx + px;
                int oc = ocg * 4 + j * 2;
                atomicAdd(&out[(oc * HOUT + oy) * HOUT + ox], __uint_as_float(lo));
                atomicAdd(&out[((oc + 1) * HOUT + oy) * HOUT + ox], __uint_as_float(hi));
            }
}

// ---------------- one conv work-unit (round-9 convoc block body) ------------------
// unit -> (tile, ic-slice, oc-half). Thread: 4 oc x (2x1) px in an 8x8 tile.
template<int LAYER, int ICS>
__device__ void conv_unit(int unit, const float* __restrict__ convs_w, float* smem)
{
    constexpr int HIN  = 256 >> LAYER;
    constexpr int HOUT = HIN >> 1;
    constexpr int TILESX = HOUT >> 3;
    constexpr int NTILES = TILESX * TILESX;
    constexpr int NSLICES = 64 / ICS;

    const int tile = unit % NTILES;
    int rest = unit / NTILES;
    const int ic0 = (rest % NSLICES) * ICS;
    const int ocb = (rest / NSLICES) * 32;
    const int ty = tile / TILESX, tx = tile - ty * TILESX;
    const int oy0 = ty * 8, ox0 = tx * 8;

    const float* __restrict__ in  = g_accs + Offs<LAYER - 1>::v;
    float* __restrict__ out       = g_accs + Offs<LAYER>::v;
    const float* __restrict__ w   = convs_w + (LAYER - 1) * 36864;
    const float* __restrict__ scl = g_scale + (LAYER - 1) * 64;
    const float* __restrict__ shf = g_shift + (LAYER - 1) * 64;

    float* s_w  = smem;                 // ICS*288
    float* s_in = smem + ICS * 288;     // ICS*340

    const int tid = threadIdx.x;

    constexpr int WPO2 = ICS * 9 / 2;
    constexpr int W2 = 32 * WPO2;
    constexpr int W2IT = (W2 + 255) / 256;
    float2 wq[W2IT];
    #pragma unroll
    for (int i = 0; i < W2IT; i++) {
        int idx = tid + i * 256;
        if (idx < W2) {
            int ocl = idx / WPO2, rem2 = idx - ocl * WPO2;
            wq[i] = *reinterpret_cast<const float2*>(&w[(ocb + ocl) * 576 + ic0 * 9 + rem2 * 2]);
        }
    }

    constexpr int ITOT = ICS * 289;
    constexpr int IIT = (ITOT + 255) / 256;
    float it[IIT];
    const int iy0 = oy0 * 2 - 1, ix0 = ox0 * 2 - 1;
    #pragma unroll
    for (int i = 0; i < IIT; i++) {
        int idx = tid + i * 256;
        if (idx < ITOT) {
            int ch = idx / 289, pos = idx - ch * 289;
            int r = pos / 17, c = pos - r * 17;
            int gy = iy0 + r, gx = ix0 + c;
            bool inb = ((unsigned)gy < (unsigned)HIN) && ((unsigned)gx < (unsigned)HIN);
            it[i] = inb ? __ldg(&in[(ic0 + ch) * HIN * HIN + gy * HIN + gx]) : 0.0f;
        }
    }

    #pragma unroll
    for (int i = 0; i < W2IT; i++) {
        int idx = tid + i * 256;
        if (idx < W2) {
            int ocl = idx / WPO2, rem2 = idx - ocl * WPO2;
            int f0 = rem2 * 2;
            int ic_a = f0 / 9, k_a = f0 - ic_a * 9;
            s_w[(ic_a * 9 + k_a) * 32 + ocl] = wq[i].x;
            int f1 = f0 + 1;
            int ic_b = f1 / 9, k_b = f1 - ic_b * 9;
            s_w[(ic_b * 9 + k_b) * 32 + ocl] = wq[i].y;
        }
    }
    #pragma unroll
    for (int i = 0; i < IIT; i++) {
        int idx = tid + i * 256;
        if (idx < ITOT) {
            int ch = idx / 289, pos = idx - ch * 289;
            int r = pos / 17, c = pos - r * 17;
            int ic = ic0 + ch;
            s_in[ch * 340 + r * 20 + c] =
                fmaxf(fmaf(it[i], __ldg(&scl[ic]), __ldg(&shf[ic])), 0.0f);
        }
    }
    __syncthreads();

    const int ocg = tid & 7;
    const int sps = tid >> 3;
    const int my = sps >> 3, mx = sps & 7;

    ull acc[2][2];
    #pragma unroll
    for (int j = 0; j < 2; j++) { acc[j][0] = 0ull; acc[j][1] = 0ull; }

    const float* bp = s_in + (4 * my) * 20 + 2 * mx;

    float2 a2[5]; float a1[5];
    #pragma unroll
    for (int r = 0; r < 5; r++) {
        a2[r] = *reinterpret_cast<const float2*>(bp + r * 20);
        a1[r] = bp[r * 20 + 2];
    }

    #pragma unroll
    for (int icc = 0; icc < ICS; icc++) {
        float2 b2[5]; float b1[5];
        if (icc + 1 < ICS) {
            const float* bpn = bp + (icc + 1) * 340;
            #pragma unroll
            for (int r = 0; r < 5; r++) {
                b2[r] = *reinterpret_cast<const float2*>(bpn + r * 20);
                b1[r] = bpn[r * 20 + 2];
            }
        }
        float win[5][3];
        #pragma unroll
        for (int r = 0; r < 5; r++) {
            win[r][0] = a2[r].x; win[r][1] = a2[r].y; win[r][2] = a1[r];
        }
        #pragma unroll
        for (int ky = 0; ky < 3; ky++)
            #pragma unroll
            for (int kx = 0; kx < 3; kx++) {
                const int k = ky * 3 + kx;
                ulonglong2 wv = *reinterpret_cast<const ulonglong2*>(
                    s_w + (icc * 9 + k) * 32 + ocg * 4);
                #pragma unroll
                for (int py = 0; py < 2; py++) {
                    ull v2;
                    PACK2(v2, win[ky + 2 * py][kx]);
                    FMA2(acc[0][py], v2, wv.x);
                    FMA2(acc[1][py], v2, wv.y);
                }
            }
        if (icc + 1 < ICS) {
            #pragma unroll
            for (int r = 0; r < 5; r++) { a2[r] = b2[r]; a1[r] = b1[r]; }
        }
    }

    #pragma unroll
    for (int j = 0; j < 2; j++)
        #pragma unroll
        for (int py = 0; py < 2; py++) {
            unsigned lo, hi;
            UNPACK2(lo, hi, acc[j][py]);
            int oy = oy0 + 2 * my + py, ox = ox0 + mx;
            int oc = ocb + ocg * 4 + j * 2;
            atomicAdd(&out[(oc * HOUT + oy) * HOUT + ox],       __uint_as_float(lo));
            atomicAdd(&out[((oc + 1) * HOUT + oy) * HOUT + ox], __uint_as_float(hi));
        }
}

// ---------------- fused tail: conv2 + conv3 + conv4 + head, one kernel -----------
// 296 blocks (2/SM guaranteed resident by launch bounds + smem budget) with
// grid-wide generation barriers between layers. Removes 3 kernel boundaries.
__global__ void __launch_bounds__(256, 2) tail_kernel(
    const float* __restrict__ convs_w,
    const float* __restrict__ head_w,
    const float* __restrict__ head_b,
    int* __restrict__ outp)
{
    __shared__ __align__(16) float smem[8 * 288 + 8 * 340];   // 20.1 KB (conv2 size)

    // conv2: 16 tiles x 8 ic-slices x 2 oc-halves = 256 units
    for (int u = blockIdx.x; u < 256; u += gridDim.x) {
        __syncthreads();
        conv_unit<2, 8>(u, convs_w, smem);
    }
    gsync();

    // conv3: 4 x 16 x 2 = 128 units
    for (int u = blockIdx.x; u < 128; u += gridDim.x) {
        __syncthreads();
        conv_unit<3, 4>(u, convs_w, smem);
    }
    gsync();

    // conv4: 1 x 32 x 2 = 64 units
    for (int u = blockIdx.x; u < 64; u += gridDim.x) {
        __syncthreads();
        conv_unit<4, 2>(u, convs_w, smem);
    }
    gsync();

    // head on block 0
    if (blockIdx.x == 0) {
        const int tid = threadIdx.x;
        __shared__ float l0[64], l1[64];
        if (tid < 64) {
            int c = tid;
            const float* a4 = g_accs + Offs<4>::v;
            float sc = g_scale[256 + c], sh = g_shift[256 + c];
            float s = 0.0f;
            #pragma unroll 8
            for (int p = 0; p < 64; p++) s += fmaxf(fmaf(a4[c * 64 + p], sc, sh), 0.0f);
            float feat = s * (1.0f / 64.0f);
            l0[c] = feat * head_w[c];
            l1[c] = feat * head_w[64 + c];
        }
        __syncthreads();
        if (tid == 0) {
            float A = head_b[0], B = head_b[1];
            for (int i = 0; i < 64; i++) { A += l0[i]; B += l1[i]; }
            outp[0] = (B > A) ? 1 : 0;
        }
    }
}

// ---------------- launch (4 graph nodes) ----------------
extern "C" void kernel_launch(void* const* d_in, const int* in_sizes, int n_in,
                              void* d_out, int out_size)
{
    const float* image   = (const float*)d_in[0];
    const float* conv0_w = (const float*)d_in[1];
    const float* conv0_b = (const float*)d_in[2];
    const float* convs_w = (const float*)d_in[3];
    const float* convs_b = (const float*)d_in[4];
    const float* bn_g    = (const float*)d_in[5];
    const float* bn_b    = (const float*)d_in[6];
    const float* bn_m    = (const float*)d_in[7];
    const float* bn_v    = (const float*)d_in[8];
    const float* head_w  = (const float*)d_in[9];
    const float* head_b  = (const float*)d_in[10];
    int* outp = (int*)d_out;

    scan_kernel<<<1056, 256>>>(image, conv0_b, convs_b, bn_g, bn_b, bn_m, bn_v);
    front_kernel<<<256, 256>>>(image, conv0_w);
    conv88_kernel<1, 8><<<dim3(64, 8), 256>>>(convs_w);   // 512 blocks
    tail_kernel<<<296, 256>>>(convs_w, head_w, head_b, outp);
}

// round 11
// speedup vs baseline: 1.0363x; 1.0363x over previous
#include <cuda_runtime.h>
#include <math.h>

#define IMG_W 8192
typedef unsigned long long ull;

// ---------------- scratch ----------------
// acc0 64x128x128 @0, acc1 64x64x64 @1048576, acc2 64x32x32 @1310720,
// acc3 64x16x16 @1376256, acc4 64x8x8 @1392640
__device__ float g_accs[1396736];
__device__ int   g_bounds[4] = {1 << 30, -1, 1 << 30, -1};  // idempotent atomics -> replay-safe
__device__ float g_scale[320];
__device__ float g_shift[320];
__device__ unsigned g_done;

#define PACK2(dst, v)  asm("mov.b64 %0, {%1, %1};" : "=l"(dst) : "r"(__float_as_uint(v)))
#define FMA2(acc, a, b) asm("fma.rn.f32x2 %0, %1, %2, %0;" : "+l"(acc) : "l"(a), "l"(b))
#define UNPACK2(lo, hi, v) asm("mov.b64 {%0, %1}, %2;" : "=r"(lo), "=r"(hi) : "l"(v))

template<int L> struct Offs;
template<> struct Offs<0> { static const int v = 0; };
template<> struct Offs<1> { static const int v = 1048576; };
template<> struct Offs<2> { static const int v = 1310720; };
template<> struct Offs<3> { static const int v = 1376256; };
template<> struct Offs<4> { static const int v = 1392640; };

// ---------------- scan (merged with prep work) ------------------------------------
__global__ void scan_kernel(const float* __restrict__ img,
                            const float* __restrict__ conv0_b,
                            const float* __restrict__ convs_b,
                            const float* __restrict__ gamma,
                            const float* __restrict__ beta,
                            const float* __restrict__ mean,
                            const float* __restrict__ var)
{
    __shared__ int smn[256], smx[256];
    const int b = blockIdx.x, tid = threadIdx.x;
    const int gid = b * 256 + tid;

    for (int k = gid; k < 348160; k += 1056 * 256) g_accs[1048576 + k] = 0.0f;
    if (gid < 320) {
        int l = gid >> 6, c = gid & 63;
        float sc = gamma[gid] / sqrtf(var[gid] + 1e-5f);
        float bb = (l == 0) ? conv0_b[c] : convs_b[(l - 1) * 64 + c];
        g_scale[gid] = sc;
        g_shift[gid] = (bb - mean[gid]) * sc + beta[gid];
    }
    if (gid == 0) g_done = 0u;

    int mn = 1 << 30, mx = -1;
    int lo_idx, hi_idx;
    if (b < 32) {                     // column scan, early exit
        lo_idx = 2; hi_idx = 3;
        int c = b * 256 + tid;
        float ref = img[c];
        bool found = false;
        for (int r = 1; r < IMG_W; r++) {
            found |= (img[(size_t)r * IMG_W + c] != ref);
            if (__all_sync(0xffffffffu, found)) break;
        }
        if (found) { mn = c; mx = c; }
    } else {                          // row scan, warp per row
        lo_idx = 0; hi_idx = 1;
        int row = (b - 32) * 8 + (tid >> 5);
        int lane = tid & 31;
        const float* rowp = img + (size_t)row * IMG_W;
        float v = rowp[lane];
        float ref = __shfl_sync(0xffffffffu, v, 0);
        int flag = __any_sync(0xffffffffu, v != ref) ? 1 : 0;
        for (int base = 32; base < IMG_W && !flag; base += 32)
            flag = __any_sync(0xffffffffu, rowp[base + lane] != ref) ? 1 : 0;
        if (lane == 0 && flag) { mn = row; mx = row; }
    }

    smn[tid] = mn; smx[tid] = mx;
    __syncthreads();
    for (int s = 128; s > 0; s >>= 1) {
        if (tid < s) { smn[tid] = min(smn[tid], smn[tid + s]); smx[tid] = max(smx[tid], smx[tid + s]); }
        __syncthreads();
    }
    if (tid == 0 && smx[0] >= 0) {
        atomicMin(&g_bounds[lo_idx], smn[0]);
        atomicMax(&g_bounds[hi_idx], smx[0]);
    }
}

// ---------------- fused crop/resize + dilate + conv0 (8x8 tiles, 256 blocks) -----
__global__ void front_kernel(const float* __restrict__ img, const float* __restrict__ w0)
{
    __shared__ float s_res[21 * 21];
    __shared__ float s_dil[17 * 17];
    __shared__ float s_w[576];
    const int b = blockIdx.x, tid = threadIdx.x;
    const int ty = b >> 4, tx = b & 15;
    const int oy0 = ty * 8, ox0 = tx * 8;

    int top = g_bounds[0], bottom = g_bounds[1], left = g_bounds[2], right = g_bounds[3];
    if (bottom < 0) { top = 0; bottom = IMG_W - 1; }
    if (right  < 0) { left = 0; right  = IMG_W - 1; }

    for (int i = tid; i < 576; i += 256) s_w[i] = w0[i];

    const int ry0 = 2 * oy0 - 3, rx0 = 2 * ox0 - 3;
    const float szy = (float)(bottom - top + 1);
    const float szx = (float)(right - left + 1);
    for (int i = tid; i < 21 * 21; i += 256) {
        int r = i / 21, c = i - r * 21;
        int gy = ry0 + r, gx = rx0 + c;
        float val = 0.0f;
        if ((unsigned)gy < 256u && (unsigned)gx < 256u) {
            float cy = (float)top  + ((float)gy + 0.5f) * szy * (1.0f / 256.0f) - 0.5f;
            float cx = (float)left + ((float)gx + 0.5f) * szx * (1.0f / 256.0f) - 0.5f;
            float fy0 = floorf(cy), fx0 = floorf(cx);
            float wy = cy - fy0, wx = cx - fx0;
            int y0 = (int)fminf(fmaxf(fy0,        (float)top),  (float)bottom);
            int y1 = (int)fminf(fmaxf(fy0 + 1.0f, (float)top),  (float)bottom);
            int x0 = (int)fminf(fmaxf(fx0,        (float)left), (float)right);
            int x1 = (int)fminf(fmaxf(fx0 + 1.0f, (float)left), (float)right);
            float v00 = img[(size_t)y0 * IMG_W + x0];
            float v01 = img[(size_t)y0 * IMG_W + x1];
            float v10 = img[(size_t)y1 * IMG_W + x0];
            float v11 = img[(size_t)y1 * IMG_W + x1];
            float tr = v00 * (1.0f - wx) + v01 * wx;
            float br = v10 * (1.0f - wx) + v11 * wx;
            val = 255.0f - (tr * (1.0f - wy) + br * wy);
        }
        s_res[i] = val;
    }
    __syncthreads();

    for (int i = tid; i < 17 * 17; i += 256) {
        int r = i / 17, c = i - r * 17;
        int gy = 2 * oy0 - 1 + r, gx = 2 * ox0 - 1 + c;
        float val = 0.0f;
        if ((unsigned)gy < 256u && (unsigned)gx < 256u) {
            float s = 0.0f;
            #pragma unroll
            for (int dy = 0; dy <= 4; dy += 2)
                #pragma unroll
                for (int dx = 0; dx <= 4; dx += 2)
                    s += s_res[(r + dy) * 21 + (c + dx)];
            val = 255.0f - fminf(fmaxf(s, 0.0f), 255.0f);
        }
        s_dil[i] = val;
    }
    __syncthreads();

    const int px = tid >> 2, ocq = tid & 3;
    const int ly = px >> 3, lx = px & 7;
    float v[9];
    #pragma unroll
    for (int ky = 0; ky < 3; ky++)
        #pragma unroll
        for (int kx = 0; kx < 3; kx++)
            v[ky * 3 + kx] = s_dil[(2 * ly + ky) * 17 + (2 * lx + kx)];

    const int oy = oy0 + ly, ox = ox0 + lx;
    #pragma unroll 4
    for (int j = 0; j < 16; j++) {
        int oc = ocq * 16 + j;
        float a = 0.0f;
        #pragma unroll
        for (int k = 0; k < 9; k++) a = fmaf(v[k], s_w[oc * 9 + k], a);
        g_accs[(oc * 128 + oy) * 128 + ox] = a;
    }
}

// ---------------- conv1: 8x8-tile, all-64-oc kernel (champion, unchanged) --------
template<int LAYER, int ICS>
__global__ void __launch_bounds__(256, 3) conv88_kernel(const float* __restrict__ convs_w)
{
    constexpr int HIN  = 256 >> LAYER;
    constexpr int HOUT = HIN >> 1;
    constexpr int TILESX = HOUT >> 3;
    const int tile = blockIdx.x;
    const int ty = tile / TILESX, tx = tile - ty * TILESX;
    const int oy0 = ty * 8, ox0 = tx * 8;
    const int ic0 = blockIdx.y * ICS;

    const float* __restrict__ in  = g_accs + Offs<LAYER - 1>::v;
    float* __restrict__ out       = g_accs + Offs<LAYER>::v;
    const float* __restrict__ w   = convs_w + (LAYER - 1) * 36864;
    const float* __restrict__ scl = g_scale + (LAYER - 1) * 64;
    const float* __restrict__ shf = g_shift + (LAYER - 1) * 64;

    __shared__ __align__(16) float s_w[ICS * 576];
    __shared__ __align__(16) float s_in[ICS * 340];

    const int tid = threadIdx.x;

    constexpr int WPO2 = ICS * 9 / 2;
    constexpr int W2 = 64 * WPO2;
    constexpr int W2IT = (W2 + 255) / 256;
    float2 wq[W2IT];
    #pragma unroll
    for (int i = 0; i < W2IT; i++) {
        int idx = tid + i * 256;
        if (idx < W2) {
            int oc = idx / WPO2, rem2 = idx - oc * WPO2;
            wq[i] = *reinterpret_cast<const float2*>(&w[oc * 576 + ic0 * 9 + rem2 * 2]);
        }
    }

    constexpr int ITOT = ICS * 289;
    constexpr int IIT = (ITOT + 255) / 256;
    float it[IIT];
    const int iy0 = oy0 * 2 - 1, ix0 = ox0 * 2 - 1;
    #pragma unroll
    for (int i = 0; i < IIT; i++) {
        int idx = tid + i * 256;
        if (idx < ITOT) {
            int ch = idx / 289, pos = idx - ch * 289;
            int r = pos / 17, c = pos - r * 17;
            int gy = iy0 + r, gx = ix0 + c;
            bool inb = ((unsigned)gy < (unsigned)HIN) && ((unsigned)gx < (unsigned)HIN);
            it[i] = inb ? __ldg(&in[(ic0 + ch) * HIN * HIN + gy * HIN + gx]) : 0.0f;
        }
    }

    #pragma unroll
    for (int i = 0; i < W2IT; i++) {
        int idx = tid + i * 256;
        if (idx < W2) {
            int oc = idx / WPO2, rem2 = idx - oc * WPO2;
            int f0 = rem2 * 2;
            int ic_a = f0 / 9, k_a = f0 - ic_a * 9;
            s_w[(ic_a * 9 + k_a) * 64 + oc] = wq[i].x;
            int f1 = f0 + 1;
            int ic_b = f1 / 9, k_b = f1 - ic_b * 9;
            s_w[(ic_b * 9 + k_b) * 64 + oc] = wq[i].y;
        }
    }
    #pragma unroll
    for (int i = 0; i < IIT; i++) {
        int idx = tid + i * 256;
        if (idx < ITOT) {
            int ch = idx / 289, pos = idx - ch * 289;
            int r = pos / 17, c = pos - r * 17;
            int ic = ic0 + ch;
            s_in[ch * 340 + r * 20 + c] =
                fmaxf(fmaf(it[i], __ldg(&scl[ic]), __ldg(&shf[ic])), 0.0f);
        }
    }
    __syncthreads();

    const int ocg = tid & 15;
    const int sps = tid >> 4;
    const int my = sps >> 2, mx = sps & 3;

    ull acc[2][4];
    #pragma unroll
    for (int j = 0; j < 2; j++)
        #pragma unroll
        for (int p = 0; p < 4; p++) acc[j][p] = 0ull;

    const float* bp = s_in + (4 * my) * 20 + 4 * mx;

    float4 q[5]; float e[5];
    #pragma unroll
    for (int r = 0; r < 5; r++) {
        q[r] = *reinterpret_cast<const float4*>(bp + r * 20);
        e[r] = bp[r * 20 + 4];
    }

    #pragma unroll
    for (int icc = 0; icc < ICS; icc++) {
        float4 qn[5]; float en[5];
        if (icc + 1 < ICS) {
            const float* bpn = bp + (icc + 1) * 340;
            #pragma unroll
            for (int r = 0; r < 5; r++) {
                qn[r] = *reinterpret_cast<const float4*>(bpn + r * 20);
                en[r] = bpn[r * 20 + 4];
            }
        }
        float win[5][5];
        #pragma unroll
        for (int r = 0; r < 5; r++) {
            win[r][0] = q[r].x; win[r][1] = q[r].y;
            win[r][2] = q[r].z; win[r][3] = q[r].w; win[r][4] = e[r];
        }
        #pragma unroll
        for (int ky = 0; ky < 3; ky++)
            #pragma unroll
            for (int kx = 0; kx < 3; kx++) {
                const int k = ky * 3 + kx;
                ulonglong2 wv = reinterpret_cast<const ulonglong2*>(s_w)[(icc * 9 + k) * 16 + ocg];
                #pragma unroll
                for (int py = 0; py < 2; py++)
                    #pragma unroll
                    for (int px = 0; px < 2; px++) {
                        ull v2;
                        PACK2(v2, win[2 * py + ky][2 * px + kx]);
                        const int p = py * 2 + px;
                        FMA2(acc[0][p], v2, wv.x);
                        FMA2(acc[1][p], v2, wv.y);
                    }
            }
        if (icc + 1 < ICS) {
            #pragma unroll
            for (int r = 0; r < 5; r++) { q[r] = qn[r]; e[r] = en[r]; }
        }
    }

    #pragma unroll
    for (int j = 0; j < 2; j++)
        #pragma unroll
        for (int py = 0; py < 2; py++)
            #pragma unroll
            for (int px = 0; px < 2; px++) {
                unsigned lo, hi;
                UNPACK2(lo, hi, acc[j][py * 2 + px]);
                int oy = oy0 + 2 * my + py, ox = ox0 + 2 * mx + px;
                int oc = ocg * 4 + j * 2;
                atomicAdd(&out[(oc * HOUT + oy) * HOUT + ox], __uint_as_float(lo));
                atomicAdd(&out[((oc + 1) * HOUT + oy) * HOUT + ox], __uint_as_float(hi));
            }
}

// ---------------- conv2-4: 8x8-tile, 16-oc-QUARTER split, 1-px threads -----------
// oc-split is atomic-neutral and weight-traffic-neutral (total weight LDG equals
// round-9's 32-oc version). 2x the blocks (conv2: 512 -> ~3.5/SM resident), and
// the 1-px thread tile cuts the inner loop to ~42 instr/icc (1 LDS.128 weight +
// 1 PACK + 2 FMA2 per k). Low regs (launch_bounds 256,4) -> 4 blocks/SM possible.
template<int LAYER, int ICS, bool HEAD>
__global__ void __launch_bounds__(256, 4) convq_kernel(
    const float* __restrict__ convs_w,
    const float* __restrict__ head_w,
    const float* __restrict__ head_b,
    int* __restrict__ outp)
{
    constexpr int HIN  = 256 >> LAYER;
    constexpr int HOUT = HIN >> 1;
    constexpr int TILESX = HOUT >> 3;
    const int tile = blockIdx.x;
    const int ty = tile / TILESX, tx = tile - ty * TILESX;
    const int oy0 = ty * 8, ox0 = tx * 8;
    const int ic0 = blockIdx.y * ICS;
    const int ocb = blockIdx.z * 16;

    const float* __restrict__ in  = g_accs + Offs<LAYER - 1>::v;
    float* __restrict__ out       = g_accs + Offs<LAYER>::v;
    const float* __restrict__ w   = convs_w + (LAYER - 1) * 36864;
    const float* __restrict__ scl = g_scale + (LAYER - 1) * 64;
    const float* __restrict__ shf = g_shift + (LAYER - 1) * 64;

    __shared__ __align__(16) float s_w[ICS * 144];   // [(icc*9+k)*16 + ocl]
    __shared__ __align__(16) float s_in[ICS * 340];  // 17 rows x 20 cols padded

    const int tid = threadIdx.x;

    // batched weight staging (float2 runs, 16 ocs)
    constexpr int WPO2 = ICS * 9 / 2;
    constexpr int W2 = 16 * WPO2;
    constexpr int W2IT = (W2 + 255) / 256;
    float2 wq[W2IT];
    #pragma unroll
    for (int i = 0; i < W2IT; i++) {
        int idx = tid + i * 256;
        if (idx < W2) {
            int ocl = idx / WPO2, rem2 = idx - ocl * WPO2;
            wq[i] = *reinterpret_cast<const float2*>(&w[(ocb + ocl) * 576 + ic0 * 9 + rem2 * 2]);
        }
    }

    // batched input staging (17x17 per ic)
    constexpr int ITOT = ICS * 289;
    constexpr int IIT = (ITOT + 255) / 256;
    float it[IIT];
    const int iy0 = oy0 * 2 - 1, ix0 = ox0 * 2 - 1;
    #pragma unroll
    for (int i = 0; i < IIT; i++) {
        int idx = tid + i * 256;
        if (idx < ITOT) {
            int ch = idx / 289, pos = idx - ch * 289;
            int r = pos / 17, c = pos - r * 17;
            int gy = iy0 + r, gx = ix0 + c;
            bool inb = ((unsigned)gy < (unsigned)HIN) && ((unsigned)gx < (unsigned)HIN);
            it[i] = inb ? __ldg(&in[(ic0 + ch) * HIN * HIN + gy * HIN + gx]) : 0.0f;
        }
    }

    #pragma unroll
    for (int i = 0; i < W2IT; i++) {
        int idx = tid + i * 256;
        if (idx < W2) {
            int ocl = idx / WPO2, rem2 = idx - ocl * WPO2;
            int f0 = rem2 * 2;
            int ic_a = f0 / 9, k_a = f0 - ic_a * 9;
            s_w[(ic_a * 9 + k_a) * 16 + ocl] = wq[i].x;
            int f1 = f0 + 1;
            int ic_b = f1 / 9, k_b = f1 - ic_b * 9;
            s_w[(ic_b * 9 + k_b) * 16 + ocl] = wq[i].y;
        }
    }
    #pragma unroll
    for (int i = 0; i < IIT; i++) {
        int idx = tid + i * 256;
        if (idx < ITOT) {
            int ch = idx / 289, pos = idx - ch * 289;
            int r = pos / 17, c = pos - r * 17;
            int ic = ic0 + ch;
            s_in[ch * 340 + r * 20 + c] =
                fmaxf(fmaf(it[i], __ldg(&scl[ic]), __ldg(&shf[ic])), 0.0f);
        }
    }
    __syncthreads();

    const int ocg = tid & 3;           // 4 oc-groups of 4 (within the 16-oc quarter)
    const int sps = tid >> 2;          // 64 px slots = full 8x8 tile, 1 px/thread
    const int my = sps >> 3, mx = sps & 7;

    ull acc0 = 0ull, acc1 = 0ull;      // {oc0,oc1}, {oc2,oc3}

    const float* bp = s_in + (2 * my) * 20 + 2 * mx;   // 8B-aligned

    float2 a2[3]; float a1[3];
    #pragma unroll
    for (int r = 0; r < 3; r++) {
        a2[r] = *reinterpret_cast<const float2*>(bp + r * 20);
        a1[r] = bp[r * 20 + 2];
    }

    #pragma unroll
    for (int icc = 0; icc < ICS; icc++) {
        float2 b2[3]; float b1[3];
        if (icc + 1 < ICS) {
            const float* bpn = bp + (icc + 1) * 340;
            #pragma unroll
            for (int r = 0; r < 3; r++) {
                b2[r] = *reinterpret_cast<const float2*>(bpn + r * 20);
                b1[r] = bpn[r * 20 + 2];
            }
        }
        float win[3][3];
        #pragma unroll
        for (int r = 0; r < 3; r++) {
            win[r][0] = a2[r].x; win[r][1] = a2[r].y; win[r][2] = a1[r];
        }
        #pragma unroll
        for (int ky = 0; ky < 3; ky++)
            #pragma unroll
            for (int kx = 0; kx < 3; kx++) {
                const int k = ky * 3 + kx;
                ulonglong2 wv = *reinterpret_cast<const ulonglong2*>(
                    s_w + (icc * 9 + k) * 16 + ocg * 4);
                ull v2;
                PACK2(v2, win[ky][kx]);
                FMA2(acc0, v2, wv.x);
                FMA2(acc1, v2, wv.y);
            }
        if (icc + 1 < ICS) {
            #pragma unroll
            for (int r = 0; r < 3; r++) { a2[r] = b2[r]; a1[r] = b1[r]; }
        }
    }

    const int oy = oy0 + my, ox = ox0 + mx;
    const int oc = ocb + ocg * 4;
    {
        unsigned lo, hi;
        UNPACK2(lo, hi, acc0);
        atomicAdd(&out[(oc * HOUT + oy) * HOUT + ox],       __uint_as_float(lo));
        atomicAdd(&out[((oc + 1) * HOUT + oy) * HOUT + ox], __uint_as_float(hi));
        UNPACK2(lo, hi, acc1);
        atomicAdd(&out[((oc + 2) * HOUT + oy) * HOUT + ox], __uint_as_float(lo));
        atomicAdd(&out[((oc + 3) * HOUT + oy) * HOUT + ox], __uint_as_float(hi));
    }

    // ---- fused head on the last-finishing conv4 block ----
    if (HEAD) {
        __shared__ unsigned s_last;
        __shared__ float l0[64], l1[64];
        __threadfence();
        __syncthreads();
        if (tid == 0) {
            unsigned total = gridDim.x * gridDim.y * gridDim.z;
            s_last = (atomicAdd(&g_done, 1u) == total - 1) ? 1u : 0u;
        }
        __syncthreads();
        if (s_last) {
            if (tid < 64) {
                __threadfence();
                int c = tid;
                const float* a4 = g_accs + Offs<4>::v;
                float sc = g_scale[256 + c], sh = g_shift[256 + c];
                float s = 0.0f;
                #pragma unroll 8
                for (int p = 0; p < 64; p++) s += fmaxf(fmaf(a4[c * 64 + p], sc, sh), 0.0f);
                float feat = s * (1.0f / 64.0f);
                l0[c] = feat * head_w[c];
                l1[c] = feat * head_w[64 + c];
            }
            __syncthreads();
            if (tid == 0) {
                float A = head_b[0], B = head_b[1];
                for (int i = 0; i < 64; i++) { A += l0[i]; B += l1[i]; }
                outp[0] = (B > A) ? 1 : 0;
            }
        }
    }
}

// ---------------- launch (6 graph nodes) ----------------
extern "C" void kernel_launch(void* const* d_in, const int* in_sizes, int n_in,
                              void* d_out, int out_size)
{
    const float* image   = (const float*)d_in[0];
    const float* conv0_w = (const float*)d_in[1];
    const float* conv0_b = (const float*)d_in[2];
    const float* convs_w = (const float*)d_in[3];
    const float* convs_b = (const float*)d_in[4];
    const float* bn_g    = (const float*)d_in[5];
    const float* bn_b    = (const float*)d_in[6];
    const float* bn_m    = (const float*)d_in[7];
    const float* bn_v    = (const float*)d_in[8];
    const float* head_w  = (const float*)d_in[9];
    const float* head_b  = (const float*)d_in[10];
    int* outp = (int*)d_out;

    scan_kernel<<<1056, 256>>>(image, conv0_b, convs_b, bn_g, bn_b, bn_m, bn_v);
    front_kernel<<<256, 256>>>(image, conv0_w);
    conv88_kernel<1, 8><<<dim3(64, 8), 256>>>(convs_w);                                 // 512
    convq_kernel<2, 8, false><<<dim3(16,  8, 4), 256>>>(convs_w, head_w, head_b, outp); // 512
    convq_kernel<3, 4, false><<<dim3( 4, 16, 4), 256>>>(convs_w, head_w, head_b, outp); // 256
    convq_kernel<4, 2, true ><<<dim3( 1, 32, 4), 256>>>(convs_w, head_w, head_b, outp); // 128
}

// round 12
// speedup vs baseline: 1.0660x; 1.0287x over previous
#include <cuda_runtime.h>
#include <math.h>

#define IMG_W 8192
typedef unsigned long long ull;

// ---------------- scratch ----------------
// acc0 64x128x128 @0, acc1 64x64x64 @1048576, acc2 64x32x32 @1310720,
// acc3 64x16x16 @1376256, acc4 64x8x8 @1392640
__device__ float g_accs[1396736];
__device__ int   g_bounds[4] = {1 << 30, -1, 1 << 30, -1};  // idempotent atomics -> replay-safe
__device__ float g_scale[320];
__device__ float g_shift[320];
__device__ unsigned g_done;

#define PACK2(dst, v)  asm("mov.b64 %0, {%1, %1};" : "=l"(dst) : "r"(__float_as_uint(v)))
#define FMA2(acc, a, b) asm("fma.rn.f32x2 %0, %1, %2, %0;" : "+l"(acc) : "l"(a), "l"(b))
#define UNPACK2(lo, hi, v) asm("mov.b64 {%0, %1}, %2;" : "=r"(lo), "=r"(hi) : "l"(v))

template<int L> struct Offs;
template<> struct Offs<0> { static const int v = 0; };
template<> struct Offs<1> { static const int v = 1048576; };
template<> struct Offs<2> { static const int v = 1310720; };
template<> struct Offs<3> { static const int v = 1376256; };
template<> struct Offs<4> { static const int v = 1392640; };

// ---------------- scan (merged with prep work) ------------------------------------
__global__ void scan_kernel(const float* __restrict__ img,
                            const float* __restrict__ conv0_b,
                            const float* __restrict__ convs_b,
                            const float* __restrict__ gamma,
                            const float* __restrict__ beta,
                            const float* __restrict__ mean,
                            const float* __restrict__ var)
{
    __shared__ int smn[256], smx[256];
    const int b = blockIdx.x, tid = threadIdx.x;
    const int gid = b * 256 + tid;

    for (int k = gid; k < 348160; k += 1056 * 256) g_accs[1048576 + k] = 0.0f;
    if (gid < 320) {
        int l = gid >> 6, c = gid & 63;
        float sc = gamma[gid] / sqrtf(var[gid] + 1e-5f);
        float bb = (l == 0) ? conv0_b[c] : convs_b[(l - 1) * 64 + c];
        g_scale[gid] = sc;
        g_shift[gid] = (bb - mean[gid]) * sc + beta[gid];
    }
    if (gid == 0) g_done = 0u;

    int mn = 1 << 30, mx = -1;
    int lo_idx, hi_idx;
    if (b < 32) {                     // column scan, early exit
        lo_idx = 2; hi_idx = 3;
        int c = b * 256 + tid;
        float ref = img[c];
        bool found = false;
        for (int r = 1; r < IMG_W; r++) {
            found |= (img[(size_t)r * IMG_W + c] != ref);
            if (__all_sync(0xffffffffu, found)) break;
        }
        if (found) { mn = c; mx = c; }
    } else {                          // row scan, warp per row
        lo_idx = 0; hi_idx = 1;
        int row = (b - 32) * 8 + (tid >> 5);
        int lane = tid & 31;
        const float* rowp = img + (size_t)row * IMG_W;
        float v = rowp[lane];
        float ref = __shfl_sync(0xffffffffu, v, 0);
        int flag = __any_sync(0xffffffffu, v != ref) ? 1 : 0;
        for (int base = 32; base < IMG_W && !flag; base += 32)
            flag = __any_sync(0xffffffffu, rowp[base + lane] != ref) ? 1 : 0;
        if (lane == 0 && flag) { mn = row; mx = row; }
    }

    smn[tid] = mn; smx[tid] = mx;
    __syncthreads();
    for (int s = 128; s > 0; s >>= 1) {
        if (tid < s) { smn[tid] = min(smn[tid], smn[tid + s]); smx[tid] = max(smx[tid], smx[tid + s]); }
        __syncthreads();
    }
    if (tid == 0 && smx[0] >= 0) {
        atomicMin(&g_bounds[lo_idx], smn[0]);
        atomicMax(&g_bounds[hi_idx], smx[0]);
    }
}

// ---------------- fused crop/resize + dilate + conv0 (8x8 tiles, 256 blocks) -----
__global__ void front_kernel(const float* __restrict__ img, const float* __restrict__ w0)
{
    __shared__ float s_res[21 * 21];
    __shared__ float s_dil[17 * 17];
    __shared__ float s_w[576];
    const int b = blockIdx.x, tid = threadIdx.x;
    const int ty = b >> 4, tx = b & 15;
    const int oy0 = ty * 8, ox0 = tx * 8;

    int top = g_bounds[0], bottom = g_bounds[1], left = g_bounds[2], right = g_bounds[3];
    if (bottom < 0) { top = 0; bottom = IMG_W - 1; }
    if (right  < 0) { left = 0; right  = IMG_W - 1; }

    for (int i = tid; i < 576; i += 256) s_w[i] = w0[i];

    const int ry0 = 2 * oy0 - 3, rx0 = 2 * ox0 - 3;
    const float szy = (float)(bottom - top + 1);
    const float szx = (float)(right - left + 1);
    for (int i = tid; i < 21 * 21; i += 256) {
        int r = i / 21, c = i - r * 21;
        int gy = ry0 + r, gx = rx0 + c;
        float val = 0.0f;
        if ((unsigned)gy < 256u && (unsigned)gx < 256u) {
            float cy = (float)top  + ((float)gy + 0.5f) * szy * (1.0f / 256.0f) - 0.5f;
            float cx = (float)left + ((float)gx + 0.5f) * szx * (1.0f / 256.0f) - 0.5f;
            float fy0 = floorf(cy), fx0 = floorf(cx);
            float wy = cy - fy0, wx = cx - fx0;
            int y0 = (int)fminf(fmaxf(fy0,        (float)top),  (float)bottom);
            int y1 = (int)fminf(fmaxf(fy0 + 1.0f, (float)top),  (float)bottom);
            int x0 = (int)fminf(fmaxf(fx0,        (float)left), (float)right);
            int x1 = (int)fminf(fmaxf(fx0 + 1.0f, (float)left), (float)right);
            float v00 = img[(size_t)y0 * IMG_W + x0];
            float v01 = img[(size_t)y0 * IMG_W + x1];
            float v10 = img[(size_t)y1 * IMG_W + x0];
            float v11 = img[(size_t)y1 * IMG_W + x1];
            float tr = v00 * (1.0f - wx) + v01 * wx;
            float br = v10 * (1.0f - wx) + v11 * wx;
            val = 255.0f - (tr * (1.0f - wy) + br * wy);
        }
        s_res[i] = val;
    }
    __syncthreads();

    for (int i = tid; i < 17 * 17; i += 256) {
        int r = i / 17, c = i - r * 17;
        int gy = 2 * oy0 - 1 + r, gx = 2 * ox0 - 1 + c;
        float val = 0.0f;
        if ((unsigned)gy < 256u && (unsigned)gx < 256u) {
            float s = 0.0f;
            #pragma unroll
            for (int dy = 0; dy <= 4; dy += 2)
                #pragma unroll
                for (int dx = 0; dx <= 4; dx += 2)
                    s += s_res[(r + dy) * 21 + (c + dx)];
            val = 255.0f - fminf(fmaxf(s, 0.0f), 255.0f);
        }
        s_dil[i] = val;
    }
    __syncthreads();

    const int px = tid >> 2, ocq = tid & 3;
    const int ly = px >> 3, lx = px & 7;
    float v[9];
    #pragma unroll
    for (int ky = 0; ky < 3; ky++)
        #pragma unroll
        for (int kx = 0; kx < 3; kx++)
            v[ky * 3 + kx] = s_dil[(2 * ly + ky) * 17 + (2 * lx + kx)];

    const int oy = oy0 + ly, ox = ox0 + lx;
    #pragma unroll 4
    for (int j = 0; j < 16; j++) {
        int oc = ocq * 16 + j;
        float a = 0.0f;
        #pragma unroll
        for (int k = 0; k < 9; k++) a = fmaf(v[k], s_w[oc * 9 + k], a);
        g_accs[(oc * 128 + oy) * 128 + ox] = a;
    }
}

// ---------------- conv1: 8x8-tile, all-64-oc kernel (champion, unchanged) --------
template<int LAYER, int ICS>
__global__ void __launch_bounds__(256, 3) conv88_kernel(const float* __restrict__ convs_w)
{
    constexpr int HIN  = 256 >> LAYER;
    constexpr int HOUT = HIN >> 1;
    constexpr int TILESX = HOUT >> 3;
    const int tile = blockIdx.x;
    const int ty = tile / TILESX, tx = tile - ty * TILESX;
    const int oy0 = ty * 8, ox0 = tx * 8;
    const int ic0 = blockIdx.y * ICS;

    const float* __restrict__ in  = g_accs + Offs<LAYER - 1>::v;
    float* __restrict__ out       = g_accs + Offs<LAYER>::v;
    const float* __restrict__ w   = convs_w + (LAYER - 1) * 36864;
    const float* __restrict__ scl = g_scale + (LAYER - 1) * 64;
    const float* __restrict__ shf = g_shift + (LAYER - 1) * 64;

    __shared__ __align__(16) float s_w[ICS * 576];
    __shared__ __align__(16) float s_in[ICS * 340];

    const int tid = threadIdx.x;

    constexpr int WPO2 = ICS * 9 / 2;
    constexpr int W2 = 64 * WPO2;
    constexpr int W2IT = (W2 + 255) / 256;
    float2 wq[W2IT];
    #pragma unroll
    for (int i = 0; i < W2IT; i++) {
        int idx = tid + i * 256;
        if (idx < W2) {
            int oc = idx / WPO2, rem2 = idx - oc * WPO2;
            wq[i] = *reinterpret_cast<const float2*>(&w[oc * 576 + ic0 * 9 + rem2 * 2]);
        }
    }

    constexpr int ITOT = ICS * 289;
    constexpr int IIT = (ITOT + 255) / 256;
    float it[IIT];
    const int iy0 = oy0 * 2 - 1, ix0 = ox0 * 2 - 1;
    #pragma unroll
    for (int i = 0; i < IIT; i++) {
        int idx = tid + i * 256;
        if (idx < ITOT) {
            int ch = idx / 289, pos = idx - ch * 289;
            int r = pos / 17, c = pos - r * 17;
            int gy = iy0 + r, gx = ix0 + c;
            bool inb = ((unsigned)gy < (unsigned)HIN) && ((unsigned)gx < (unsigned)HIN);
            it[i] = inb ? __ldg(&in[(ic0 + ch) * HIN * HIN + gy * HIN + gx]) : 0.0f;
        }
    }

    #pragma unroll
    for (int i = 0; i < W2IT; i++) {
        int idx = tid + i * 256;
        if (idx < W2) {
            int oc = idx / WPO2, rem2 = idx - oc * WPO2;
            int f0 = rem2 * 2;
            int ic_a = f0 / 9, k_a = f0 - ic_a * 9;
            s_w[(ic_a * 9 + k_a) * 64 + oc] = wq[i].x;
            int f1 = f0 + 1;
            int ic_b = f1 / 9, k_b = f1 - ic_b * 9;
            s_w[(ic_b * 9 + k_b) * 64 + oc] = wq[i].y;
        }
    }
    #pragma unroll
    for (int i = 0; i < IIT; i++) {
        int idx = tid + i * 256;
        if (idx < ITOT) {
            int ch = idx / 289, pos = idx - ch * 289;
            int r = pos / 17, c = pos - r * 17;
            int ic = ic0 + ch;
            s_in[ch * 340 + r * 20 + c] =
                fmaxf(fmaf(it[i], __ldg(&scl[ic]), __ldg(&shf[ic])), 0.0f);
        }
    }
    __syncthreads();

    const int ocg = tid & 15;
    const int sps = tid >> 4;
    const int my = sps >> 2, mx = sps & 3;

    ull acc[2][4];
    #pragma unroll
    for (int j = 0; j < 2; j++)
        #pragma unroll
        for (int p = 0; p < 4; p++) acc[j][p] = 0ull;

    const float* bp = s_in + (4 * my) * 20 + 4 * mx;

    float4 q[5]; float e[5];
    #pragma unroll
    for (int r = 0; r < 5; r++) {
        q[r] = *reinterpret_cast<const float4*>(bp + r * 20);
        e[r] = bp[r * 20 + 4];
    }

    #pragma unroll
    for (int icc = 0; icc < ICS; icc++) {
        float4 qn[5]; float en[5];
        if (icc + 1 < ICS) {
            const float* bpn = bp + (icc + 1) * 340;
            #pragma unroll
            for (int r = 0; r < 5; r++) {
                qn[r] = *reinterpret_cast<const float4*>(bpn + r * 20);
                en[r] = bpn[r * 20 + 4];
            }
        }
        float win[5][5];
        #pragma unroll
        for (int r = 0; r < 5; r++) {
            win[r][0] = q[r].x; win[r][1] = q[r].y;
            win[r][2] = q[r].z; win[r][3] = q[r].w; win[r][4] = e[r];
        }
        #pragma unroll
        for (int ky = 0; ky < 3; ky++)
            #pragma unroll
            for (int kx = 0; kx < 3; kx++) {
                const int k = ky * 3 + kx;
                ulonglong2 wv = reinterpret_cast<const ulonglong2*>(s_w)[(icc * 9 + k) * 16 + ocg];
                #pragma unroll
                for (int py = 0; py < 2; py++)
                    #pragma unroll
                    for (int px = 0; px < 2; px++) {
                        ull v2;
                        PACK2(v2, win[2 * py + ky][2 * px + kx]);
                        const int p = py * 2 + px;
                        FMA2(acc[0][p], v2, wv.x);
                        FMA2(acc[1][p], v2, wv.y);
                    }
            }
        if (icc + 1 < ICS) {
            #pragma unroll
            for (int r = 0; r < 5; r++) { q[r] = qn[r]; e[r] = en[r]; }
        }
    }

    #pragma unroll
    for (int j = 0; j < 2; j++)
        #pragma unroll
        for (int py = 0; py < 2; py++)
            #pragma unroll
            for (int px = 0; px < 2; px++) {
                unsigned lo, hi;
                UNPACK2(lo, hi, acc[j][py * 2 + px]);
                int oy = oy0 + 2 * my + py, ox = ox0 + 2 * mx + px;
                int oc = ocg * 4 + j * 2;
                atomicAdd(&out[(oc * HOUT + oy) * HOUT + ox], __uint_as_float(lo));
                atomicAdd(&out[((oc + 1) * HOUT + oy) * HOUT + ox], __uint_as_float(hi));
            }
}

// ---------------- conv2-4: round-9 convoc with DUPLICATED-INPUT smem -------------
// Input smem holds {v,v} f32x2 pairs -> mainloop broadcast operands come straight
// from LDS (no PACK2 MOVs). Per icc per thread: 9 LDS.128(w) + 5 LDS.128 +
// 5 LDS.64 (input) + 36 FMA2 = 55 instr (round 9: 78). Grids/tiles/atomics
// identical to round 9. Thread: 4 oc x (2x1) px; 8 oc-groups x 32 spatial slots.
template<int LAYER, int ICS, bool HEAD>
__global__ void __launch_bounds__(256, 2) convoc_kernel(
    const float* __restrict__ convs_w,
    const float* __restrict__ head_w,
    const float* __restrict__ head_b,
    int* __restrict__ outp)
{
    constexpr int HIN  = 256 >> LAYER;
    constexpr int HOUT = HIN >> 1;
    constexpr int TILESX = HOUT >> 3;
    constexpr int RSTR = 36;            // floats per dup row (17 pairs -> pad 36)
    constexpr int CSTR = 17 * RSTR;     // 612 floats per channel
    const int tile = blockIdx.x;
    const int ty = tile / TILESX, tx = tile - ty * TILESX;
    const int oy0 = ty * 8, ox0 = tx * 8;
    const int ic0 = blockIdx.y * ICS;
    const int ocb = blockIdx.z * 32;

    const float* __restrict__ in  = g_accs + Offs<LAYER - 1>::v;
    float* __restrict__ out       = g_accs + Offs<LAYER>::v;
    const float* __restrict__ w   = convs_w + (LAYER - 1) * 36864;
    const float* __restrict__ scl = g_scale + (LAYER - 1) * 64;
    const float* __restrict__ shf = g_shift + (LAYER - 1) * 64;

    __shared__ __align__(16) float s_w[ICS * 288];   // [(icc*9+k)*32 + ocl]
    __shared__ __align__(16) float s_in[ICS * CSTR]; // dup pairs [ch][r][c][2]

    const int tid = threadIdx.x;

    // batched weight staging (float2 runs, 32 ocs)
    constexpr int WPO2 = ICS * 9 / 2;
    constexpr int W2 = 32 * WPO2;
    constexpr int W2IT = (W2 + 255) / 256;
    float2 wq[W2IT];
    #pragma unroll
    for (int i = 0; i < W2IT; i++) {
        int idx = tid + i * 256;
        if (idx < W2) {
            int ocl = idx / WPO2, rem2 = idx - ocl * WPO2;
            wq[i] = *reinterpret_cast<const float2*>(&w[(ocb + ocl) * 576 + ic0 * 9 + rem2 * 2]);
        }
    }

    // batched input staging (17x17 per ic)
    constexpr int ITOT = ICS * 289;
    constexpr int IIT = (ITOT + 255) / 256;
    float it[IIT];
    const int iy0 = oy0 * 2 - 1, ix0 = ox0 * 2 - 1;
    #pragma unroll
    for (int i = 0; i < IIT; i++) {
        int idx = tid + i * 256;
        if (idx < ITOT) {
            int ch = idx / 289, pos = idx - ch * 289;
            int r = pos / 17, c = pos - r * 17;
            int gy = iy0 + r, gx = ix0 + c;
            bool inb = ((unsigned)gy < (unsigned)HIN) && ((unsigned)gx < (unsigned)HIN);
            it[i] = inb ? __ldg(&in[(ic0 + ch) * HIN * HIN + gy * HIN + gx]) : 0.0f;
        }
    }

    #pragma unroll
    for (int i = 0; i < W2IT; i++) {
        int idx = tid + i * 256;
        if (idx < W2) {
            int ocl = idx / WPO2, rem2 = idx - ocl * WPO2;
            int f0 = rem2 * 2;
            int ic_a = f0 / 9, k_a = f0 - ic_a * 9;
            s_w[(ic_a * 9 + k_a) * 32 + ocl] = wq[i].x;
            int f1 = f0 + 1;
            int ic_b = f1 / 9, k_b = f1 - ic_b * 9;
            s_w[(ic_b * 9 + k_b) * 32 + ocl] = wq[i].y;
        }
    }
    #pragma unroll
    for (int i = 0; i < IIT; i++) {
        int idx = tid + i * 256;
        if (idx < ITOT) {
            int ch = idx / 289, pos = idx - ch * 289;
            int r = pos / 17, c = pos - r * 17;
            int ic = ic0 + ch;
            float vv = fmaxf(fmaf(it[i], __ldg(&scl[ic]), __ldg(&shf[ic])), 0.0f);
            ull dv; PACK2(dv, vv);
            *reinterpret_cast<ull*>(&s_in[ch * CSTR + r * RSTR + c * 2]) = dv;
        }
    }
    __syncthreads();

    const int ocg = tid & 7;           // 8 oc-groups of 4
    const int sps = tid >> 3;          // 32 slots: 4x8 grid of 2x1 micros
    const int my = sps >> 3, mx = sps & 7;

    ull acc[2][2];                     // [oc pair][py]
    #pragma unroll
    for (int j = 0; j < 2; j++) { acc[j][0] = 0ull; acc[j][1] = 0ull; }

    // window base: rows 4my..4my+4, dup-pair cols 2mx..2mx+2 (16B aligned)
    const float* bp = s_in + (4 * my) * RSTR + (2 * mx) * 2;

    ulonglong2 a01[5]; ull a2[5];
    #pragma unroll
    for (int r = 0; r < 5; r++) {
        a01[r] = *reinterpret_cast<const ulonglong2*>(bp + r * RSTR);
        a2[r]  = *reinterpret_cast<const ull*>(bp + r * RSTR + 4);
    }

    #pragma unroll
    for (int icc = 0; icc < ICS; icc++) {
        ulonglong2 b01[5]; ull b2[5];
        if (icc + 1 < ICS) {
            const float* bpn = bp + (icc + 1) * CSTR;
            #pragma unroll
            for (int r = 0; r < 5; r++) {
                b01[r] = *reinterpret_cast<const ulonglong2*>(bpn + r * RSTR);
                b2[r]  = *reinterpret_cast<const ull*>(bpn + r * RSTR + 4);
            }
        }
        ull win[5][3];
        #pragma unroll
        for (int r = 0; r < 5; r++) {
            win[r][0] = a01[r].x; win[r][1] = a01[r].y; win[r][2] = a2[r];
        }
        #pragma unroll
        for (int ky = 0; ky < 3; ky++)
            #pragma unroll
            for (int kx = 0; kx < 3; kx++) {
                const int k = ky * 3 + kx;
                ulonglong2 wv = *reinterpret_cast<const ulonglong2*>(
                    s_w + (icc * 9 + k) * 32 + ocg * 4);
                #pragma unroll
                for (int py = 0; py < 2; py++) {
                    ull v2 = win[ky + 2 * py][kx];
                    FMA2(acc[0][py], v2, wv.x);
                    FMA2(acc[1][py], v2, wv.y);
                }
            }
        if (icc + 1 < ICS) {
            #pragma unroll
            for (int r = 0; r < 5; r++) { a01[r] = b01[r]; a2[r] = b2[r]; }
        }
    }

    #pragma unroll
    for (int j = 0; j < 2; j++)
        #pragma unroll
        for (int py = 0; py < 2; py++) {
            unsigned lo, hi;
            UNPACK2(lo, hi, acc[j][py]);
            int oy = oy0 + 2 * my + py, ox = ox0 + mx;
            int oc = ocb + ocg * 4 + j * 2;
            atomicAdd(&out[(oc * HOUT + oy) * HOUT + ox],       __uint_as_float(lo));
            atomicAdd(&out[((oc + 1) * HOUT + oy) * HOUT + ox], __uint_as_float(hi));
        }

    // ---- fused head on the last-finishing conv4 block ----
    if (HEAD) {
        __shared__ unsigned s_last;
        __shared__ float l0[64], l1[64];
        __threadfence();
        __syncthreads();
        if (tid == 0) {
            unsigned total = gridDim.x * gridDim.y * gridDim.z;
            s_last = (atomicAdd(&g_done, 1u) == total - 1) ? 1u : 0u;
        }
        __syncthreads();
        if (s_last) {
            if (tid < 64) {
                __threadfence();
                int c = tid;
                const float* a4 = g_accs + Offs<4>::v;
                float sc = g_scale[256 + c], sh = g_shift[256 + c];
                float s = 0.0f;
                #pragma unroll 8
                for (int p = 0; p < 64; p++) s += fmaxf(fmaf(a4[c * 64 + p], sc, sh), 0.0f);
                float feat = s * (1.0f / 64.0f);
                l0[c] = feat * head_w[c];
                l1[c] = feat * head_w[64 + c];
            }
            __syncthreads();
            if (tid == 0) {
                float A = head_b[0], B = head_b[1];
                for (int i = 0; i < 64; i++) { A += l0[i]; B += l1[i]; }
                outp[0] = (B > A) ? 1 : 0;
            }
        }
    }
}

// ---------------- launch (6 graph nodes) ----------------
extern "C" void kernel_launch(void* const* d_in, const int* in_sizes, int n_in,
                              void* d_out, int out_size)
{
    const float* image   = (const float*)d_in[0];
    const float* conv0_w = (const float*)d_in[1];
    const float* conv0_b = (const float*)d_in[2];
    const float* convs_w = (const float*)d_in[3];
    const float* convs_b = (const float*)d_in[4];
    const float* bn_g    = (const float*)d_in[5];
    const float* bn_b    = (const float*)d_in[6];
    const float* bn_m    = (const float*)d_in[7];
    const float* bn_v    = (const float*)d_in[8];
    const float* head_w  = (const float*)d_in[9];
    const float* head_b  = (const float*)d_in[10];
    int* outp = (int*)d_out;

    scan_kernel<<<1056, 256>>>(image, conv0_b, convs_b, bn_g, bn_b, bn_m, bn_v);
    front_kernel<<<256, 256>>>(image, conv0_w);
    conv88_kernel<1, 8><<<dim3(64, 8), 256>>>(convs_w);                                  // 512
    convoc_kernel<2, 8, false><<<dim3(16,  8, 2), 256>>>(convs_w, head_w, head_b, outp); // 256
    convoc_kernel<3, 4, false><<<dim3( 4, 16, 2), 256>>>(convs_w, head_w, head_b, outp); // 128
    convoc_kernel<4, 2, true ><<<dim3( 1, 32, 2), 256>>>(convs_w, head_w, head_b, outp); //  64
}